// round 5
// baseline (speedup 1.0000x reference)
#include <cuda_runtime.h>
#include <math.h>

#define BATCH   4096
#define LIN     4448
#define LP      278      // after conv1(s4)+maxpool4
#define L2OUT   139      // conv2 output length
#define NQ      8
#define SD      256
#define NLAY    3

__device__ float g_feat[BATCH * SD];   // scratch: [B, 256] extractor features

// ---------- packed f32x2 helpers ----------
__device__ __forceinline__ unsigned long long splat2(float x) {
    unsigned long long r; unsigned u = __float_as_uint(x);
    asm("mov.b64 %0, {%1, %1};" : "=l"(r) : "r"(u));
    return r;
}
__device__ __forceinline__ unsigned long long fma2(unsigned long long a,
                                                   unsigned long long b,
                                                   unsigned long long c) {
    unsigned long long d;
    asm("fma.rn.f32x2 %0, %1, %2, %3;" : "=l"(d) : "l"(a), "l"(b), "l"(c));
    return d;
}
__device__ __forceinline__ float2 unpack2(unsigned long long v) {
    unsigned lo, hi;
    asm("mov.b64 {%0, %1}, %2;" : "=r"(lo), "=r"(hi) : "l"(v));
    return make_float2(__uint_as_float(lo), __uint_as_float(hi));
}

// ---------------- Kernel 1: conv stack, TWO samples per block, sample-pair f32x2 ----
// smem (floats): region A is flux (interleaved pairs) then reused for h2 output
#define SM_FXH2  0                        // max(flux 8960, h2 32*286=9152) = 9152
#define SM_POOLD 9152                     // pool pairs: 16 rows x 594 floats (297 pairs)
#define SM_W1    (SM_POOLD + 16*594)      // 240
#define SM_W2T   (SM_W1 + 240)            // [112][32] = 3584
#define SM_BN1S  (SM_W2T + 3584)
#define SM_BN1B  (SM_BN1S + 16)
#define SM_BN2S  (SM_BN1B + 16)
#define SM_BN2B  (SM_BN2S + 32)
#define SM1_TOTAL (SM_BN2B + 32)          // 22576 floats = 90304 B -> 2 blocks/SM

__global__ void __launch_bounds__(256, 2) k_conv(
    const float* __restrict__ flux,
    const float* __restrict__ w1, const float* __restrict__ g1, const float* __restrict__ b1,
    const float* __restrict__ w2, const float* __restrict__ g2, const float* __restrict__ b2)
{
    extern __shared__ float sm[];
    const int tid = threadIdx.x;
    const int sA = blockIdx.x * 2, sB = sA + 1;

    // zero flux guards (pairs 0..7 and 4456..4575) and pool region
    if (tid < 16) sm[SM_FXH2 + tid] = 0.f;
    for (int i = 8912 + tid; i < 9152; i += 256) sm[SM_FXH2 + i] = 0.f;
    for (int i = tid; i < 16*594; i += 256) sm[SM_POOLD + i] = 0.f;

    // stage both flux rows interleaved: pair idx 8+i = {fluxA[i], fluxB[i]}
    {
        const float* fA = flux + (size_t)sA * LIN;
        const float* fB = flux + (size_t)sB * LIN;
        for (int i = tid; i < LIN; i += 256) {
            float2 v = make_float2(__ldg(fA + i), __ldg(fB + i));
            *(float2*)&sm[SM_FXH2 + 16 + 2*i] = v;
        }
    }
    for (int i = tid; i < 240; i += 256) sm[SM_W1 + i] = w1[i];
    for (int i = tid; i < 3584; i += 256) {
        int c2 = i / 112, ck = i % 112;
        sm[SM_W2T + ck*32 + c2] = w2[i];
    }
    const float inv_eps = rsqrtf(1.0f + 1e-5f);
    if (tid < 16) { sm[SM_BN1S + tid] = g1[tid] * inv_eps; sm[SM_BN1B + tid] = b1[tid]; }
    if (tid >= 32 && tid < 64) { sm[SM_BN2S + tid-32] = g2[tid-32] * inv_eps; sm[SM_BN2B + tid-32] = b2[tid-32]; }
    __syncthreads();

    // conv1 (k=15,s=4,p=7) + BN + ReLU + MaxPool4; thread = (channel, pos-group)
    {
        const int c = tid & 15, jg = tid >> 4;       // warp: 2 jg x 16 c
        unsigned long long wk[15];
        #pragma unroll
        for (int k = 0; k < 15; k++) wk[k] = splat2(sm[SM_W1 + c*15 + k]);
        const float sc = sm[SM_BN1S + c], bt = sm[SM_BN1B + c];
        for (int j = jg; j < LP; j += 16) {
            // guarded pair index: orig pos base = 16j-7 -> pair idx 16j+1
            const float* fbase = sm + SM_FXH2 + 2*(16*j + 1);
            unsigned long long a0 = 0ull, a1 = 0ull, a2 = 0ull, a3 = 0ull;
            #pragma unroll
            for (int t = 0; t < 27; t++) {
                unsigned long long fs = *(const unsigned long long*)(fbase + 2*t);
                if (t < 15)            a0 = fma2(wk[t],    fs, a0);
                if (t >= 4 && t < 19)  a1 = fma2(wk[t-4],  fs, a1);
                if (t >= 8 && t < 23)  a2 = fma2(wk[t-8],  fs, a2);
                if (t >= 12)           a3 = fma2(wk[t-12], fs, a3);
            }
            float2 v0 = unpack2(a0), v1 = unpack2(a1), v2 = unpack2(a2), v3 = unpack2(a3);
            float mx = fmaxf(fmaxf(v0.x, v1.x), fmaxf(v2.x, v3.x));
            float my = fmaxf(fmaxf(v0.y, v1.y), fmaxf(v2.y, v3.y));
            float2 o = make_float2(fmaxf(mx*sc + bt, 0.f), fmaxf(my*sc + bt, 0.f));
            *(float2*)&sm[SM_POOLD + c*594 + 2*(3 + j)] = o;
        }
    }
    __syncthreads();

    // conv2 (16->32, k=7, s=2, p=3) + BN + ReLU; thread = (out-ch, pos-group), 2 sweeps of 9
    {
        const int c2 = tid & 31, pg = tid >> 5;      // warp: all c2, same pg -> f broadcast
        const float sc = sm[SM_BN2S + c2], bt = sm[SM_BN2B + c2];
        #pragma unroll
        for (int sw = 0; sw < 2; sw++) {
            const int p0 = pg*9 + sw*72;             // covers 0..143 >= 139
            unsigned long long acc[9];
            #pragma unroll
            for (int i = 0; i < 9; i++) acc[i] = 0ull;
            #pragma unroll 4
            for (int c = 0; c < 16; c++) {
                unsigned long long wk[7];
                #pragma unroll
                for (int k = 0; k < 7; k++)
                    wk[k] = splat2(sm[SM_W2T + (c*7 + k)*32 + c2]);
                const float* fbase = sm + SM_POOLD + c*594 + 2*(2*p0);
                #pragma unroll
                for (int t = 0; t < 23; t++) {
                    unsigned long long fs = *(const unsigned long long*)(fbase + 2*t);
                    #pragma unroll
                    for (int i = 0; i < 9; i++) {
                        int k = t - 2*i;
                        if (k >= 0 && k < 7) acc[i] = fma2(wk[k], fs, acc[i]);
                    }
                }
            }
            #pragma unroll
            for (int i = 0; i < 9; i++) {
                int p = p0 + i;
                if (p < L2OUT) {
                    float2 v = unpack2(acc[i]);
                    float2 o = make_float2(fmaxf(v.x*sc + bt, 0.f), fmaxf(v.y*sc + bt, 0.f));
                    *(float2*)&sm[SM_FXH2 + c2*286 + 2*p] = o;   // h2 pairs overlay flux
                }
            }
        }
    }
    __syncthreads();

    // adaptive_avg_pool1d(139 -> 8), feature layout c*8+i, both samples
    {
        const int c = tid >> 3, i = tid & 7;
        const int st = (i * L2OUT) >> 3;
        const int en = ((i + 1) * L2OUT + 7) >> 3;
        float ax = 0.f, ay = 0.f;
        for (int p = st; p < en; p++) {
            float2 v = *(const float2*)&sm[SM_FXH2 + c*286 + 2*p];
            ax += v.x; ay += v.y;
        }
        float invn = 1.0f / (float)(en - st);
        g_feat[(size_t)sA * SD + c*8 + i] = ax * invn;
        g_feat[(size_t)sB * SD + c*8 + i] = ay * invn;
    }
}

// ---------------- Kernel 2: proj + normalize + VQC + head (R3 structure) ----------------
#define TB 16
#define S2_A 0                          // 16640: W1 [64][257] then W2 [256][65]
#define S2_B 16640                      // 16*257: feats, then state x
#define S2_C (S2_B + 16*257)            // 16*65: y1
#define S2_ROT (S2_C + 16*65)           // 24 gates x 8 matrix entries
#define SM2_TOTAL (S2_ROT + 24*8)       // 21984 floats = 87936 B

__global__ __launch_bounds__(512) void k_tail(
    const float* __restrict__ scalars,
    const float* __restrict__ W1, const float* __restrict__ B1,
    const float* __restrict__ W2, const float* __restrict__ B2,
    const float* __restrict__ qw,
    const float* __restrict__ hw1, const float* __restrict__ hb1,
    const float* __restrict__ hg,  const float* __restrict__ hbb,
    const float* __restrict__ hw2, const float* __restrict__ hb2,
    float* __restrict__ out)
{
    extern __shared__ float sm[];
    const int tid = threadIdx.x;
    const int s0 = blockIdx.x * TB;

    for (int i = tid; i < TB*SD; i += 512) {
        int sl = i >> 8, k = i & 255;
        sm[S2_B + sl*257 + k] = g_feat[(size_t)(s0 + sl)*SD + k];
    }
    for (int i = tid; i < 64*256; i += 512)
        sm[S2_A + (i >> 8)*257 + (i & 255)] = W1[i];

    // precompute the 24 Rot matrices once per block
    if (tid < NLAY*NQ) {
        float phi = __ldg(qw + tid*3 + 0);
        float th  = __ldg(qw + tid*3 + 1);
        float om  = __ldg(qw + tid*3 + 2);
        float sh, ch; sincosf(0.5f*th, &sh, &ch);
        float sa, ca; sincosf(0.5f*(phi + om), &sa, &ca);
        float sb, cb; sincosf(0.5f*(phi - om), &sb, &cb);
        float* u = sm + S2_ROT + tid*8;
        u[0] =  ca*ch;  u[1] = -sa*ch;
        u[2] = -cb*sh;  u[3] = -sb*sh;
        u[4] =  cb*sh;  u[5] = -sb*sh;
        u[6] =  ca*ch;  u[7] =  sa*ch;
    }
    __syncthreads();

    // proj1: y1[s][j] = relu(b1[j] + feat[s]·W1[j]); thread = (j, sample-pair)
    {
        const int j = tid >> 3, sg = tid & 7;
        float acc0, acc1;
        const float bb = __ldg(B1 + j);
        acc0 = bb; acc1 = bb;
        const float* wrow = sm + S2_A + j*257;
        const float* f0 = sm + S2_B + (sg*2 + 0)*257;
        const float* f1 = sm + S2_B + (sg*2 + 1)*257;
        for (int k = 0; k < 256; k++) {
            float w = wrow[k];
            acc0 += w * f0[k];
            acc1 += w * f1[k];
        }
        sm[S2_C + (sg*2 + 0)*65 + j] = fmaxf(acc0, 0.f);
        sm[S2_C + (sg*2 + 1)*65 + j] = fmaxf(acc1, 0.f);
    }
    __syncthreads();
    for (int i = tid; i < 256*64; i += 512)
        sm[S2_A + (i >> 6)*65 + (i & 63)] = W2[i];
    __syncthreads();

    // proj2: x[s][m] = b2[m] + y1[s]·W2[m]; thread = (m, 8-sample group)
    {
        const int m = tid & 255, sg = tid >> 8;
        float acc[8];
        const float bb = __ldg(B2 + m);
        #pragma unroll
        for (int si = 0; si < 8; si++) acc[si] = bb;
        const float* wrow = sm + S2_A + m*65;
        for (int j = 0; j < 64; j++) {
            float w = wrow[j];
            #pragma unroll
            for (int si = 0; si < 8; si++)
                acc[si] += sm[S2_C + (sg*8 + si)*65 + j] * w;
        }
        #pragma unroll
        for (int si = 0; si < 8; si++) sm[S2_B + (sg*8 + si)*257 + m] = acc[si];
    }
    __syncthreads();

    // one warp per sample: normalize + 8-qubit/3-layer circuit in registers + head
    const int warp = tid >> 5, lane = tid & 31;
    const unsigned FULL = 0xffffffffu;
    {
        const int sl = warp;
        const int gs = s0 + sl;
        float are[8], aim[8];
        float sq = 0.f;
        #pragma unroll
        for (int m = 0; m < 8; m++) {
            float v = sm[S2_B + sl*257 + lane*8 + m];
            are[m] = v; aim[m] = 0.f; sq += v*v;
        }
        #pragma unroll
        for (int off = 16; off; off >>= 1) sq += __shfl_xor_sync(FULL, sq, off);
        float n   = sqrtf(sq);
        float inv = 1.0f / fmaxf(n, 1e-12f);
        if (n * inv < 1e-8f) {
            #pragma unroll
            for (int m = 0; m < 8; m++) are[m] = 0.0625f;
        } else {
            #pragma unroll
            for (int m = 0; m < 8; m++) are[m] *= inv;
        }

        for (int l = 0; l < NLAY; l++) {
            for (int q = 0; q < NQ; q++) {
                const float* u = sm + S2_ROT + (l*NQ + q)*8;
                int b = 7 - q;
                if (b >= 3) {                       // lane-bit gate, SEL-free inner loop
                    int lb = b - 3;
                    unsigned msk = 1u << lb;
                    bool hi = (lane >> lb) & 1;
                    float cmr = hi ? u[6] : u[0];
                    float cmi = hi ? u[7] : u[1];
                    float cpr = hi ? u[4] : u[2];
                    float cpi = hi ? u[5] : u[3];
                    #pragma unroll
                    for (int m = 0; m < 8; m++) {
                        float pr = __shfl_xor_sync(FULL, are[m], msk);
                        float pi = __shfl_xor_sync(FULL, aim[m], msk);
                        float mr = are[m], mi = aim[m];
                        are[m] = cmr*mr - cmi*mi + cpr*pr - cpi*pi;
                        aim[m] = cmr*mi + cmi*mr + cpr*pi + cpi*pr;
                    }
                } else {                            // register-local gate
                    float u00r = u[0], u00i = u[1], u01r = u[2], u01i = u[3];
                    float u10r = u[4], u10i = u[5], u11r = u[6], u11i = u[7];
                    int mb = 1 << b;
                    #pragma unroll
                    for (int m0 = 0; m0 < 8; m0++) {
                        if (m0 & mb) continue;
                        int m1 = m0 | mb;
                        float a0r = are[m0], a0i = aim[m0];
                        float a1r = are[m1], a1i = aim[m1];
                        are[m0] = u00r*a0r - u00i*a0i + u01r*a1r - u01i*a1i;
                        aim[m0] = u00r*a0i + u00i*a0r + u01r*a1i + u01i*a1r;
                        are[m1] = u10r*a0r - u10i*a0i + u11r*a1r - u11i*a1i;
                        aim[m1] = u10r*a0i + u10i*a0r + u11r*a1i + u11i*a1r;
                    }
                }
            }
            #pragma unroll
            for (int q = 0; q < 4; q++) {           // CNOTs with both bits in lane
                unsigned shm  = 1u << (3 - q);
                unsigned cond = 1u << (4 - q);
                bool take = (lane & cond) != 0;
                #pragma unroll
                for (int m = 0; m < 8; m++) {
                    float pr = __shfl_xor_sync(FULL, are[m], shm);
                    float pi = __shfl_xor_sync(FULL, aim[m], shm);
                    if (take) { are[m] = pr; aim[m] = pi; }
                }
            }
            if (lane & 1) {                         // CNOT(4,5)
                #pragma unroll
                for (int m = 0; m < 4; m++) {
                    float tr = are[m]; are[m] = are[m+4]; are[m+4] = tr;
                    float ti = aim[m]; aim[m] = aim[m+4]; aim[m+4] = ti;
                }
            }
            {   // CNOT(5,6): swap (4,6),(5,7); CNOT(6,7): swap (2,3),(6,7)
                float t;
                t = are[4]; are[4] = are[6]; are[6] = t;  t = aim[4]; aim[4] = aim[6]; aim[6] = t;
                t = are[5]; are[5] = are[7]; are[7] = t;  t = aim[5]; aim[5] = aim[7]; aim[7] = t;
                t = are[2]; are[2] = are[3]; are[3] = t;  t = aim[2]; aim[2] = aim[3]; aim[3] = t;
                t = are[6]; are[6] = are[7]; are[7] = t;  t = aim[6]; aim[6] = aim[7]; aim[7] = t;
            }
            #pragma unroll
            for (int m = 1; m < 8; m += 2) {        // CNOT(7,0)
                are[m] = __shfl_xor_sync(FULL, are[m], 16);
                aim[m] = __shfl_xor_sync(FULL, aim[m], 16);
            }
        }

        // <Z_q> expectations
        float S = 0.f, S5 = 0.f, S6 = 0.f, S7 = 0.f;
        #pragma unroll
        for (int m = 0; m < 8; m++) {
            float p = are[m]*are[m] + aim[m]*aim[m];
            S  += p;
            S5 += (m & 4) ? -p : p;
            S6 += (m & 2) ? -p : p;
            S7 += (m & 1) ? -p : p;
        }
        float z[8];
        z[0] = (lane & 16) ? -S : S;
        z[1] = (lane &  8) ? -S : S;
        z[2] = (lane &  4) ? -S : S;
        z[3] = (lane &  2) ? -S : S;
        z[4] = (lane &  1) ? -S : S;
        z[5] = S5; z[6] = S6; z[7] = S7;
        #pragma unroll
        for (int q = 0; q < 8; q++)
            #pragma unroll
            for (int off = 16; off; off >>= 1)
                z[q] += __shfl_xor_sync(FULL, z[q], off);

        // head: [z(8), scalars(6)] -> 32 (BN eval + relu) -> 3
        float in[14];
        #pragma unroll
        for (int k = 0; k < 8; k++) in[k] = z[k];
        #pragma unroll
        for (int k = 0; k < 6; k++) in[8 + k] = __ldg(scalars + (size_t)gs*6 + k);
        float acc = __ldg(hb1 + lane);
        #pragma unroll
        for (int k = 0; k < 14; k++) acc += in[k] * __ldg(hw1 + lane*14 + k);
        float bsc = __ldg(hg + lane) * rsqrtf(1.0f + 1e-5f);
        float h = fmaxf(acc*bsc + __ldg(hbb + lane), 0.f);
        #pragma unroll
        for (int o = 0; o < 3; o++) {
            float v = h * __ldg(hw2 + o*32 + lane);
            #pragma unroll
            for (int off = 16; off; off >>= 1) v += __shfl_xor_sync(FULL, v, off);
            if (lane == o) out[(size_t)gs*3 + o] = v + __ldg(hb2 + o);
        }
    }
}

extern "C" void kernel_launch(void* const* d_in, const int* in_sizes, int n_in,
                              void* d_out, int out_size)
{
    const float* flux    = (const float*)d_in[0];
    const float* scalars = (const float*)d_in[1];
    const float* conv1_w = (const float*)d_in[2];
    const float* bn1_g   = (const float*)d_in[3];
    const float* bn1_b   = (const float*)d_in[4];
    const float* conv2_w = (const float*)d_in[5];
    const float* bn2_g   = (const float*)d_in[6];
    const float* bn2_b   = (const float*)d_in[7];
    const float* proj_w1 = (const float*)d_in[8];
    const float* proj_b1 = (const float*)d_in[9];
    const float* proj_w2 = (const float*)d_in[10];
    const float* proj_b2 = (const float*)d_in[11];
    const float* q_w     = (const float*)d_in[12];
    const float* head_w1 = (const float*)d_in[13];
    const float* head_b1 = (const float*)d_in[14];
    const float* head_g  = (const float*)d_in[15];
    const float* head_bb = (const float*)d_in[16];
    const float* head_w2 = (const float*)d_in[17];
    const float* head_b2 = (const float*)d_in[18];
    float* out = (float*)d_out;

    int B = in_sizes[1] / 6;           // scalars [B,6]
    if (B > BATCH) B = BATCH;

    cudaFuncSetAttribute(k_conv, cudaFuncAttributeMaxDynamicSharedMemorySize, SM1_TOTAL*4);
    cudaFuncSetAttribute(k_tail, cudaFuncAttributeMaxDynamicSharedMemorySize, SM2_TOTAL*4);

    k_conv<<<B/2, 256, SM1_TOTAL*4>>>(flux, conv1_w, bn1_g, bn1_b, conv2_w, bn2_g, bn2_b);
    k_tail<<<B/TB, 512, SM2_TOTAL*4>>>(scalars, proj_w1, proj_b1, proj_w2, proj_b2,
                                       q_w, head_w1, head_b1, head_g, head_bb,
                                       head_w2, head_b2, out);
}

// round 6
// speedup vs baseline: 1.7186x; 1.7186x over previous
#include <cuda_runtime.h>
#include <math.h>

#define BATCH   4096
#define LIN     4448
#define LP      278      // after conv1(s4)+maxpool4: 1112/4
#define L2OUT   139      // conv2 output length
#define NQ      8
#define SD      256
#define NLAY    3

__device__ float g_feat[BATCH * SD];   // scratch: [B, 256] extractor features

// ---------- packed f32x2 helpers ----------
__device__ __forceinline__ unsigned long long splat2(float x) {
    unsigned long long r; unsigned u = __float_as_uint(x);
    asm("mov.b64 %0, {%1, %1};" : "=l"(r) : "r"(u));
    return r;
}
__device__ __forceinline__ unsigned long long fma2(unsigned long long a,
                                                   unsigned long long b,
                                                   unsigned long long c) {
    unsigned long long d;
    asm("fma.rn.f32x2 %0, %1, %2, %3;" : "=l"(d) : "l"(a), "l"(b), "l"(c));
    return d;
}
__device__ __forceinline__ float2 unpack2(unsigned long long v) {
    unsigned lo, hi;
    asm("mov.b64 {%0, %1}, %2;" : "=r"(lo), "=r"(hi) : "l"(v));
    return make_float2(__uint_as_float(lo), __uint_as_float(hi));
}

// ---------------- Kernel 1: conv stack (one sample per block) ----------------
#define SM_FLUX 0
#define SM_POOL (SM_FLUX + LIN)                 // [16][284] + 16 pad, +3 halo offset
#define SM_H2   (SM_POOL + 16*284 + 16)        // [32][141]
#define SM_W1P  (SM_H2 + 32*141)               // conv1 weight pairs [15][8] float2 = 240 f
#define SM_W2P  (SM_W1P + 240)                 // conv2 weight pairs [112][16] float2 = 3584 f
#define SM_BN1S (SM_W2P + 3584)
#define SM_BN1B (SM_BN1S + 16)
#define SM_BN2S (SM_BN1B + 16)
#define SM_BN2B (SM_BN2S + 32)
#define SM1_TOTAL (SM_BN2B + 32)               // 17440 floats = 69760 B

__global__ __launch_bounds__(256) void k_conv(
    const float* __restrict__ flux,
    const float* __restrict__ w1, const float* __restrict__ g1, const float* __restrict__ b1,
    const float* __restrict__ w2, const float* __restrict__ g2, const float* __restrict__ b2)
{
    extern __shared__ float sm[];
    const int tid = threadIdx.x;
    const int s = blockIdx.x;

    // stage flux row (coalesced float4)
    const float4* fx4 = (const float4*)(flux + (size_t)s * LIN);
    for (int i = tid; i < LIN/4; i += 256) ((float4*)(sm + SM_FLUX))[i] = fx4[i];

    // conv1 weight pairs: w1p[k][cp] = {w1[cp][k], w1[cp+8][k]}
    if (tid < 120) {
        int k = tid / 8, cp = tid % 8;
        sm[SM_W1P + (k*8 + cp)*2 + 0] = w1[cp*15 + k];
        sm[SM_W1P + (k*8 + cp)*2 + 1] = w1[(cp+8)*15 + k];
    }
    // conv2 weight pairs: w2p[ck][cp] = {w2[cp][ck], w2[cp+16][ck]}
    for (int i = tid; i < 112*16; i += 256) {
        int ck = i >> 4, cp = i & 15;
        sm[SM_W2P + i*2 + 0] = w2[cp*112 + ck];
        sm[SM_W2P + i*2 + 1] = w2[(cp+16)*112 + ck];
    }
    const float inv_eps = rsqrtf(1.0f + 1e-5f);
    if (tid < 16) { sm[SM_BN1S + tid] = g1[tid] * inv_eps; sm[SM_BN1B + tid] = b1[tid]; }
    if (tid < 32) { sm[SM_BN2S + tid] = g2[tid] * inv_eps; sm[SM_BN2B + tid] = b2[tid]; }
    for (int i = tid; i < 16*284 + 16; i += 256) sm[SM_POOL + i] = 0.f;
    __syncthreads();

    // conv1 (k=15,s=4,p=7) + BN + ReLU + MaxPool4, 2 channels packed per thread
    {
        const int cp = tid & 7, jb = tid >> 3;      // 8 channel-pairs x 32 pos-groups
        unsigned long long wp[15];
        #pragma unroll
        for (int k = 0; k < 15; k++)
            wp[k] = *(const unsigned long long*)&sm[SM_W1P + (k*8 + cp)*2];
        const float sc0 = sm[SM_BN1S + cp],     bt0 = sm[SM_BN1B + cp];
        const float sc1 = sm[SM_BN1S + cp + 8], bt1 = sm[SM_BN1B + cp + 8];
        for (int j = jb; j < LP; j += 32) {
            const int base = 16*j - 7;
            float f[27];
            if (j >= 1 && j <= 276) {
                #pragma unroll
                for (int t = 0; t < 27; t++) f[t] = sm[SM_FLUX + base + t];
            } else {
                #pragma unroll
                for (int t = 0; t < 27; t++) {
                    int xi = base + t;
                    f[t] = (xi >= 0 && xi < LIN) ? sm[SM_FLUX + xi] : 0.f;
                }
            }
            unsigned long long a0 = 0ull, a1 = 0ull, a2 = 0ull, a3 = 0ull;
            #pragma unroll
            for (int t = 0; t < 27; t++) {
                unsigned long long fs = splat2(f[t]);
                if (t < 15)            a0 = fma2(wp[t],    fs, a0);
                if (t >= 4 && t < 19)  a1 = fma2(wp[t-4],  fs, a1);
                if (t >= 8 && t < 23)  a2 = fma2(wp[t-8],  fs, a2);
                if (t >= 12)           a3 = fma2(wp[t-12], fs, a3);
            }
            float2 v0 = unpack2(a0), v1 = unpack2(a1), v2 = unpack2(a2), v3 = unpack2(a3);
            float mlo = fmaxf(fmaxf(v0.x, v1.x), fmaxf(v2.x, v3.x));
            float mhi = fmaxf(fmaxf(v0.y, v1.y), fmaxf(v2.y, v3.y));
            sm[SM_POOL + cp*284 + 3 + j]       = fmaxf(mlo*sc0 + bt0, 0.f);
            sm[SM_POOL + (cp+8)*284 + 3 + j]   = fmaxf(mhi*sc1 + bt1, 0.f);
        }
    }
    __syncthreads();

    // conv2 (16->32, k=7, s=2, p=3) + BN + ReLU
    // 2 channels packed x 9 consecutive positions per thread, single balanced sweep.
    // t-outer ordering: each activation splat once, feeds all valid accumulators.
    {
        const int cp = tid & 15, pg = tid >> 4;     // 16 channel-pairs x 16 pos-groups
        const float sc0 = sm[SM_BN2S + cp],      bt0 = sm[SM_BN2B + cp];
        const float sc1 = sm[SM_BN2S + cp + 16], bt1 = sm[SM_BN2B + cp + 16];
        const int p0 = pg * 9;                      // covers 0..143 >= 139
        unsigned long long acc[9];
        #pragma unroll
        for (int i = 0; i < 9; i++) acc[i] = 0ull;
        #pragma unroll
        for (int c = 0; c < 16; c++) {
            float f[23];                            // window for 9 stride-2 positions
            #pragma unroll
            for (int t = 0; t < 23; t++) {
                int xi = 2*p0 + t;
                f[t] = (xi < 284) ? sm[SM_POOL + c*284 + xi] : 0.f;
            }
            unsigned long long wp[7];
            #pragma unroll
            for (int k = 0; k < 7; k++)
                wp[k] = *(const unsigned long long*)&sm[SM_W2P + ((c*7 + k)*16 + cp)*2];
            #pragma unroll
            for (int t = 0; t < 23; t++) {
                unsigned long long fs = splat2(f[t]);
                #pragma unroll
                for (int i = 0; i < 9; i++) {
                    int k = t - 2*i;
                    if (k >= 0 && k < 7) acc[i] = fma2(wp[k], fs, acc[i]);
                }
            }
        }
        #pragma unroll
        for (int i = 0; i < 9; i++) {
            if (p0 + i < L2OUT) {
                float2 v = unpack2(acc[i]);
                sm[SM_H2 + cp*141 + p0 + i]      = fmaxf(v.x*sc0 + bt0, 0.f);
                sm[SM_H2 + (cp+16)*141 + p0 + i] = fmaxf(v.y*sc1 + bt1, 0.f);
            }
        }
    }
    __syncthreads();

    // adaptive_avg_pool1d(139 -> 8), feature layout c*8+i
    {
        const int c = tid >> 3, i = tid & 7;
        const int st = (i * L2OUT) >> 3;
        const int en = ((i + 1) * L2OUT + 7) >> 3;
        float acc = 0.f;
        for (int p = st; p < en; p++) acc += sm[SM_H2 + c*141 + p];
        g_feat[(size_t)s * SD + c*8 + i] = acc / (float)(en - st);
    }
}

// ---------------- Kernel 2: proj + normalize + VQC + head (R3 verbatim, 512 thr) ----
#define TB 16
#define S2_A 0                          // 16640: W1 [64][257] then W2 [256][65]
#define S2_B 16640                      // 16*257: feats, then state x
#define S2_C (S2_B + 16*257)            // 16*65: y1
#define S2_ROT (S2_C + 16*65)           // 24 gates x 8 matrix entries
#define SM2_TOTAL (S2_ROT + 24*8)       // 21984 floats = 87936 B

__global__ __launch_bounds__(512) void k_tail(
    const float* __restrict__ scalars,
    const float* __restrict__ W1, const float* __restrict__ B1,
    const float* __restrict__ W2, const float* __restrict__ B2,
    const float* __restrict__ qw,
    const float* __restrict__ hw1, const float* __restrict__ hb1,
    const float* __restrict__ hg,  const float* __restrict__ hbb,
    const float* __restrict__ hw2, const float* __restrict__ hb2,
    float* __restrict__ out)
{
    extern __shared__ float sm[];
    const int tid = threadIdx.x;
    const int s0 = blockIdx.x * TB;

    for (int i = tid; i < TB*SD; i += 512) {
        int sl = i >> 8, k = i & 255;
        sm[S2_B + sl*257 + k] = g_feat[(size_t)(s0 + sl)*SD + k];
    }
    for (int i = tid; i < 64*256; i += 512)
        sm[S2_A + (i >> 8)*257 + (i & 255)] = W1[i];

    // precompute the 24 Rot matrices once per block
    if (tid < NLAY*NQ) {
        float phi = __ldg(qw + tid*3 + 0);
        float th  = __ldg(qw + tid*3 + 1);
        float om  = __ldg(qw + tid*3 + 2);
        float sh, ch; sincosf(0.5f*th, &sh, &ch);
        float sa, ca; sincosf(0.5f*(phi + om), &sa, &ca);
        float sb, cb; sincosf(0.5f*(phi - om), &sb, &cb);
        float* u = sm + S2_ROT + tid*8;
        u[0] =  ca*ch;  u[1] = -sa*ch;    // u00
        u[2] = -cb*sh;  u[3] = -sb*sh;    // u01
        u[4] =  cb*sh;  u[5] = -sb*sh;    // u10
        u[6] =  ca*ch;  u[7] =  sa*ch;    // u11
    }
    __syncthreads();

    // proj1: y1[s][j] = relu(b1[j] + feat[s]·W1[j]); thread = (j, sample-pair)
    {
        const int j = tid >> 3, sg = tid & 7;
        float acc0, acc1;
        const float bb = __ldg(B1 + j);
        acc0 = bb; acc1 = bb;
        const float* wrow = sm + S2_A + j*257;
        const float* f0 = sm + S2_B + (sg*2 + 0)*257;
        const float* f1 = sm + S2_B + (sg*2 + 1)*257;
        for (int k = 0; k < 256; k++) {
            float w = wrow[k];
            acc0 += w * f0[k];
            acc1 += w * f1[k];
        }
        sm[S2_C + (sg*2 + 0)*65 + j] = fmaxf(acc0, 0.f);
        sm[S2_C + (sg*2 + 1)*65 + j] = fmaxf(acc1, 0.f);
    }
    __syncthreads();
    for (int i = tid; i < 256*64; i += 512)
        sm[S2_A + (i >> 6)*65 + (i & 63)] = W2[i];
    __syncthreads();

    // proj2: x[s][m] = b2[m] + y1[s]·W2[m]; thread = (m, 8-sample group)
    {
        const int m = tid & 255, sg = tid >> 8;
        float acc[8];
        const float bb = __ldg(B2 + m);
        #pragma unroll
        for (int si = 0; si < 8; si++) acc[si] = bb;
        const float* wrow = sm + S2_A + m*65;
        for (int j = 0; j < 64; j++) {
            float w = wrow[j];
            #pragma unroll
            for (int si = 0; si < 8; si++)
                acc[si] += sm[S2_C + (sg*8 + si)*65 + j] * w;
        }
        #pragma unroll
        for (int si = 0; si < 8; si++) sm[S2_B + (sg*8 + si)*257 + m] = acc[si];
    }
    __syncthreads();

    // one warp per sample: normalize + 8-qubit/3-layer circuit in registers + head
    const int warp = tid >> 5, lane = tid & 31;
    const unsigned FULL = 0xffffffffu;
    {
        const int sl = warp;
        const int gs = s0 + sl;
        float are[8], aim[8];
        float sq = 0.f;
        #pragma unroll
        for (int m = 0; m < 8; m++) {
            float v = sm[S2_B + sl*257 + lane*8 + m];
            are[m] = v; aim[m] = 0.f; sq += v*v;
        }
        #pragma unroll
        for (int off = 16; off; off >>= 1) sq += __shfl_xor_sync(FULL, sq, off);
        float n   = sqrtf(sq);
        float inv = 1.0f / fmaxf(n, 1e-12f);
        if (n * inv < 1e-8f) {
            #pragma unroll
            for (int m = 0; m < 8; m++) are[m] = 0.0625f;   // 1/sqrt(256)
        } else {
            #pragma unroll
            for (int m = 0; m < 8; m++) are[m] *= inv;
        }

        for (int l = 0; l < NLAY; l++) {
            for (int q = 0; q < NQ; q++) {
                const float* u = sm + S2_ROT + (l*NQ + q)*8;
                float u00r = u[0], u00i = u[1], u01r = u[2], u01i = u[3];
                float u10r = u[4], u10i = u[5], u11r = u[6], u11i = u[7];
                int b = 7 - q;
                if (b >= 3) {                       // lane-bit gate
                    int lb = b - 3;
                    unsigned msk = 1u << lb;
                    bool hi = (lane >> lb) & 1;
                    float r0 = hi ? u10r : u00r, i0 = hi ? u10i : u00i;
                    float r1 = hi ? u11r : u01r, i1 = hi ? u11i : u01i;
                    #pragma unroll
                    for (int m = 0; m < 8; m++) {
                        float pr = __shfl_xor_sync(FULL, are[m], msk);
                        float pi = __shfl_xor_sync(FULL, aim[m], msk);
                        float a0r = hi ? pr : are[m], a0i = hi ? pi : aim[m];
                        float a1r = hi ? are[m] : pr, a1i = hi ? aim[m] : pi;
                        are[m] = r0*a0r - i0*a0i + r1*a1r - i1*a1i;
                        aim[m] = r0*a0i + i0*a0r + r1*a1i + i1*a1r;
                    }
                } else {                            // register-local gate
                    int mb = 1 << b;
                    #pragma unroll
                    for (int m0 = 0; m0 < 8; m0++) {
                        if (m0 & mb) continue;
                        int m1 = m0 | mb;
                        float a0r = are[m0], a0i = aim[m0];
                        float a1r = are[m1], a1i = aim[m1];
                        are[m0] = u00r*a0r - u00i*a0i + u01r*a1r - u01i*a1i;
                        aim[m0] = u00r*a0i + u00i*a0r + u01r*a1i + u01i*a1r;
                        are[m1] = u10r*a0r - u10i*a0i + u11r*a1r - u11i*a1i;
                        aim[m1] = u10r*a0i + u10i*a0r + u11r*a1i + u11i*a1r;
                    }
                }
            }
            // CNOT ring: (0,1)(1,2)...(7,0); wire q <-> state bit 7-q
            #pragma unroll
            for (int q = 0; q < 4; q++) {           // both bits in lane
                unsigned shm  = 1u << (3 - q);
                unsigned cond = 1u << (4 - q);
                bool take = (lane & cond) != 0;
                #pragma unroll
                for (int m = 0; m < 8; m++) {
                    float pr = __shfl_xor_sync(FULL, are[m], shm);
                    float pi = __shfl_xor_sync(FULL, aim[m], shm);
                    if (take) { are[m] = pr; aim[m] = pi; }
                }
            }
            if (lane & 1) {                         // CNOT(4,5): ctrl lane bit0, tgt m bit2
                #pragma unroll
                for (int m = 0; m < 4; m++) {
                    float tr = are[m]; are[m] = are[m+4]; are[m+4] = tr;
                    float ti = aim[m]; aim[m] = aim[m+4]; aim[m+4] = ti;
                }
            }
            {   // CNOT(5,6): swap (4,6),(5,7); CNOT(6,7): swap (2,3),(6,7)
                float t;
                t = are[4]; are[4] = are[6]; are[6] = t;  t = aim[4]; aim[4] = aim[6]; aim[6] = t;
                t = are[5]; are[5] = are[7]; are[7] = t;  t = aim[5]; aim[5] = aim[7]; aim[7] = t;
                t = are[2]; are[2] = are[3]; are[3] = t;  t = aim[2]; aim[2] = aim[3]; aim[3] = t;
                t = are[6]; are[6] = are[7]; are[7] = t;  t = aim[6]; aim[6] = aim[7]; aim[7] = t;
            }
            #pragma unroll
            for (int m = 1; m < 8; m += 2) {        // CNOT(7,0): ctrl m bit0, tgt lane bit4
                are[m] = __shfl_xor_sync(FULL, are[m], 16);
                aim[m] = __shfl_xor_sync(FULL, aim[m], 16);
            }
        }

        // <Z_q> expectations
        float S = 0.f, S5 = 0.f, S6 = 0.f, S7 = 0.f;
        #pragma unroll
        for (int m = 0; m < 8; m++) {
            float p = are[m]*are[m] + aim[m]*aim[m];
            S  += p;
            S5 += (m & 4) ? -p : p;
            S6 += (m & 2) ? -p : p;
            S7 += (m & 1) ? -p : p;
        }
        float z[8];
        z[0] = (lane & 16) ? -S : S;
        z[1] = (lane &  8) ? -S : S;
        z[2] = (lane &  4) ? -S : S;
        z[3] = (lane &  2) ? -S : S;
        z[4] = (lane &  1) ? -S : S;
        z[5] = S5; z[6] = S6; z[7] = S7;
        #pragma unroll
        for (int q = 0; q < 8; q++)
            #pragma unroll
            for (int off = 16; off; off >>= 1)
                z[q] += __shfl_xor_sync(FULL, z[q], off);

        // head: [z(8), scalars(6)] -> 32 (BN eval + relu) -> 3
        float in[14];
        #pragma unroll
        for (int k = 0; k < 8; k++) in[k] = z[k];
        #pragma unroll
        for (int k = 0; k < 6; k++) in[8 + k] = __ldg(scalars + (size_t)gs*6 + k);
        float acc = __ldg(hb1 + lane);
        #pragma unroll
        for (int k = 0; k < 14; k++) acc += in[k] * __ldg(hw1 + lane*14 + k);
        float bsc = __ldg(hg + lane) * rsqrtf(1.0f + 1e-5f);
        float h = fmaxf(acc*bsc + __ldg(hbb + lane), 0.f);
        #pragma unroll
        for (int o = 0; o < 3; o++) {
            float v = h * __ldg(hw2 + o*32 + lane);
            #pragma unroll
            for (int off = 16; off; off >>= 1) v += __shfl_xor_sync(FULL, v, off);
            if (lane == o) out[(size_t)gs*3 + o] = v + __ldg(hb2 + o);
        }
    }
}

extern "C" void kernel_launch(void* const* d_in, const int* in_sizes, int n_in,
                              void* d_out, int out_size)
{
    const float* flux    = (const float*)d_in[0];
    const float* scalars = (const float*)d_in[1];
    const float* conv1_w = (const float*)d_in[2];
    const float* bn1_g   = (const float*)d_in[3];
    const float* bn1_b   = (const float*)d_in[4];
    const float* conv2_w = (const float*)d_in[5];
    const float* bn2_g   = (const float*)d_in[6];
    const float* bn2_b   = (const float*)d_in[7];
    const float* proj_w1 = (const float*)d_in[8];
    const float* proj_b1 = (const float*)d_in[9];
    const float* proj_w2 = (const float*)d_in[10];
    const float* proj_b2 = (const float*)d_in[11];
    const float* q_w     = (const float*)d_in[12];
    const float* head_w1 = (const float*)d_in[13];
    const float* head_b1 = (const float*)d_in[14];
    const float* head_g  = (const float*)d_in[15];
    const float* head_bb = (const float*)d_in[16];
    const float* head_w2 = (const float*)d_in[17];
    const float* head_b2 = (const float*)d_in[18];
    float* out = (float*)d_out;

    int B = in_sizes[1] / 6;           // scalars [B,6]
    if (B > BATCH) B = BATCH;

    cudaFuncSetAttribute(k_conv, cudaFuncAttributeMaxDynamicSharedMemorySize, SM1_TOTAL*4);
    cudaFuncSetAttribute(k_tail, cudaFuncAttributeMaxDynamicSharedMemorySize, SM2_TOTAL*4);

    k_conv<<<B, 256, SM1_TOTAL*4>>>(flux, conv1_w, bn1_g, bn1_b, conv2_w, bn2_g, bn2_b);
    k_tail<<<B/TB, 512, SM2_TOTAL*4>>>(scalars, proj_w1, proj_b1, proj_w2, proj_b2,
                                       q_w, head_w1, head_b1, head_g, head_bb,
                                       head_w2, head_b2, out);
}